// round 8
// baseline (speedup 1.0000x reference)
#include <cuda_runtime.h>
#include <cstdint>

// out[b,o] = tanh( sum_{j<3} tanh(x[b]·w_in[:,j] - thr_h[j]) * w_ho[j,o] + C_o - 0.5 )
// C_o = sum_{j=3..63} tanh(-thr_h[j]) * w_ho[j,o]
//
// HBM-bound: stream x (128 MB) once via cp.async double-buffered 2-ROW tiles.
// Each thread copies and consumes ONLY its own chunks -> no barrier needed for
// the x tile (wait_group suffices). One __syncthreads per PAIR of rows (for the
// cross-warp reduce), amortizing the ~1.9us/row tail that capped R6 at 49% DRAM.

#define NTHREADS 256
#define NBLOCKS  444          // 148 SMs * 3 resident blocks
#define BATCH_N  8192
#define DIM_N    4096
#define OUT_N    8
#define NPAIRS   (BATCH_N / 2)            // 4096 row-pairs
#define ROW_BYTES (DIM_N * 4)             // 16 KB
#define PAIR_BYTES (2 * ROW_BYTES)        // 32 KB
#define SMEM_DYN (2 * PAIR_BYTES)         // 64 KB: 2 buffers x 2 rows

__device__ __forceinline__ void cp_async16(uint32_t dst_smem, const void* src) {
    asm volatile("cp.async.cg.shared.global [%0], [%1], 16;" :: "r"(dst_smem), "l"(src));
}
__device__ __forceinline__ void cp_commit() {
    asm volatile("cp.async.commit_group;");
}
__device__ __forceinline__ void cp_wait1() {
    asm volatile("cp.async.wait_group 1;");
}

extern __shared__ float4 s_x[];   // [2 buffers][2 rows][1024 float4]

__global__ void __launch_bounds__(NTHREADS, 3)
enn_kernel(const float* __restrict__ x,
           const float* __restrict__ w_in,
           const float* __restrict__ w_ho,
           const float* __restrict__ thr_h,
           float* __restrict__ out)
{
    __shared__ float s_part[2][6][8];  // [parity][row*3+j][warp]
    __shared__ float s_c[OUT_N];       // C_o - 0.5
    __shared__ float s_who[3][OUT_N];
    __shared__ float s_thr[3];

    const int t    = threadIdx.x;
    const int lane = t & 31;
    const int warp = t >> 5;

    // ---- one-time per-block prologue ----
    if (t < 24) s_who[t / 8][t % 8] = w_ho[t];          // w_ho rows 0..2
    if (t < 3)  s_thr[t] = thr_h[t];
    if (t < OUT_N) {
        float c = -0.5f;
        #pragma unroll 1
        for (int j = 3; j < 64; j++)
            c = fmaf(tanhf(-thr_h[j]), w_ho[j * OUT_N + t], c);
        s_c[t] = c;
    }

    // ---- register-cache w_in: thread t owns float4-chunks {t, t+256, t+512, t+768}
    // chunk f covers dims 4f..4f+3 -> 12 consecutive w_in floats at index 12f
    // (byte offset 48f: always 16B-aligned).
    float4 w[4][3];
    #pragma unroll
    for (int k = 0; k < 4; k++) {
        const int f = t + k * NTHREADS;
        const float4* wp = reinterpret_cast<const float4*>(w_in + 12 * f);
        w[k][0] = wp[0];
        w[k][1] = wp[1];
        w[k][2] = wp[2];
    }

    const uint32_t sx_base = (uint32_t)__cvta_generic_to_shared(&s_x[0]);

    // ---- prologue: async-copy first pair into buffer 0 ----
    int p = blockIdx.x;               // pair index; rows 2p, 2p+1 (32 KB contiguous)
    {
        const char* src = (const char*)(x + (size_t)(2 * p) * DIM_N);
        #pragma unroll
        for (int k = 0; k < 8; k++)   // 2 rows x 4 chunks, contiguous 32 KB
            cp_async16(sx_base + (uint32_t)(t * 16 + k * 4096),
                       src + t * 16 + k * 4096);
        cp_commit();
    }
    __syncthreads();   // covers s_c / s_who / s_thr init

    int parity = 0;
    for (; p < NPAIRS; p += gridDim.x, parity ^= 1) {
        const int np = p + gridDim.x;
        const int pb = parity & 1, nb = pb ^ 1;

        // issue next pair's async copy into the other buffer
        if (np < NPAIRS) {
            const char* src = (const char*)(x + (size_t)(2 * np) * DIM_N);
            #pragma unroll
            for (int k = 0; k < 8; k++)
                cp_async16(sx_base + (uint32_t)(nb * PAIR_BYTES + t * 16 + k * 4096),
                           src + t * 16 + k * 4096);
        }
        cp_commit();   // always commit so wait_group 1 leaves exactly the newest pending
        cp_wait1();    // this pair's tile complete; own-thread data -> NO barrier needed

        const float4* sxa = s_x + (pb * 2) * (DIM_N / 4);      // row 2p
        const float4* sxb = sxa + (DIM_N / 4);                 // row 2p+1

        float a0 = 0.f, a1 = 0.f, a2 = 0.f;   // row A accumulators
        float b0 = 0.f, b1 = 0.f, b2 = 0.f;   // row B accumulators
        #pragma unroll
        for (int k = 0; k < 4; k++) {
            const float4 va = sxa[t + k * NTHREADS];   // own chunks only
            const float4 vb = sxb[t + k * NTHREADS];
            // layout: W0=(d0j0,d0j1,d0j2,d1j0) W1=(d1j1,d1j2,d2j0,d2j1) W2=(d2j2,d3j0,d3j1,d3j2)
            a0 = fmaf(va.x, w[k][0].x, a0); b0 = fmaf(vb.x, w[k][0].x, b0);
            a0 = fmaf(va.y, w[k][0].w, a0); b0 = fmaf(vb.y, w[k][0].w, b0);
            a0 = fmaf(va.z, w[k][1].z, a0); b0 = fmaf(vb.z, w[k][1].z, b0);
            a0 = fmaf(va.w, w[k][2].y, a0); b0 = fmaf(vb.w, w[k][2].y, b0);

            a1 = fmaf(va.x, w[k][0].y, a1); b1 = fmaf(vb.x, w[k][0].y, b1);
            a1 = fmaf(va.y, w[k][1].x, a1); b1 = fmaf(vb.y, w[k][1].x, b1);
            a1 = fmaf(va.z, w[k][1].w, a1); b1 = fmaf(vb.z, w[k][1].w, b1);
            a1 = fmaf(va.w, w[k][2].z, a1); b1 = fmaf(vb.w, w[k][2].z, b1);

            a2 = fmaf(va.x, w[k][0].z, a2); b2 = fmaf(vb.x, w[k][0].z, b2);
            a2 = fmaf(va.y, w[k][1].y, a2); b2 = fmaf(vb.y, w[k][1].y, b2);
            a2 = fmaf(va.z, w[k][2].x, a2); b2 = fmaf(vb.z, w[k][2].x, b2);
            a2 = fmaf(va.w, w[k][2].w, a2); b2 = fmaf(vb.w, w[k][2].w, b2);
        }

        // warp tree-reduce: 6 interleaved chains (good ILP across the 30-cyc SHFL latency)
        #pragma unroll
        for (int off = 16; off > 0; off >>= 1) {
            a0 += __shfl_xor_sync(0xFFFFFFFFu, a0, off);
            b0 += __shfl_xor_sync(0xFFFFFFFFu, b0, off);
            a1 += __shfl_xor_sync(0xFFFFFFFFu, a1, off);
            b1 += __shfl_xor_sync(0xFFFFFFFFu, b1, off);
            a2 += __shfl_xor_sync(0xFFFFFFFFu, a2, off);
            b2 += __shfl_xor_sync(0xFFFFFFFFu, b2, off);
        }
        if (lane == 0) {
            s_part[pb][0][warp] = a0;
            s_part[pb][1][warp] = a1;
            s_part[pb][2][warp] = a2;
            s_part[pb][3][warp] = b0;
            s_part[pb][4][warp] = b1;
            s_part[pb][5][warp] = b2;
        }
        __syncthreads();   // single barrier per PAIR: orders s_part writes->reads;
                           // also fences s_x[pb] reuse 2 iterations later (parity).

        if (t < 16) {
            const int r = t >> 3;            // 0: row 2p, 1: row 2p+1
            const int o = t & 7;
            float s0 = 0.f, s1 = 0.f, s2 = 0.f;
            #pragma unroll
            for (int wv = 0; wv < 8; wv++) {
                s0 += s_part[pb][3 * r + 0][wv];
                s1 += s_part[pb][3 * r + 1][wv];
                s2 += s_part[pb][3 * r + 2][wv];
            }
            const float t0 = tanhf(s0 - s_thr[0]);
            const float t1 = tanhf(s1 - s_thr[1]);
            const float t2 = tanhf(s2 - s_thr[2]);
            float vv = s_c[o];
            vv = fmaf(t0, s_who[0][o], vv);
            vv = fmaf(t1, s_who[1][o], vv);
            vv = fmaf(t2, s_who[2][o], vv);
            out[(2 * p + r) * OUT_N + o] = tanhf(vv);
        }
    }
}

extern "C" void kernel_launch(void* const* d_in, const int* in_sizes, int n_in,
                              void* d_out, int out_size)
{
    const float* x     = (const float*)d_in[0];   // [8192, 4096]
    const float* w_in  = (const float*)d_in[1];   // [4096, 3]
    const float* w_ho  = (const float*)d_in[2];   // [64, 8]
    const float* thr_h = (const float*)d_in[3];   // [64]
    float* out = (float*)d_out;                   // [8192, 8]

    cudaFuncSetAttribute(enn_kernel,
                         cudaFuncAttributeMaxDynamicSharedMemorySize, SMEM_DYN);
    enn_kernel<<<NBLOCKS, NTHREADS, SMEM_DYN>>>(x, w_in, w_ho, thr_h, out);
}